// round 1
// baseline (speedup 1.0000x reference)
#include <cuda_runtime.h>

#define SEQ 2048
#define NB 8
#define DM 512
#define DK 64
#define SCALE 0.125f   // 1/sqrt(64)

// Scratch for projected Q, K, V (allocs are forbidden -> device globals)
__device__ float g_Q[NB * SEQ * DK];
__device__ float g_K[NB * SEQ * DK];
__device__ float g_V[NB * SEQ * DK];

// ---------------------------------------------------------------------------
// Projection GEMM: Y[M,64] = X[M,512] @ W[512,64] + b
// BM=128, BN=64, BK=16; 256 threads; each thread computes 8x4 micro-tile.
// blockIdx.y selects which of the 3 projections.
// ---------------------------------------------------------------------------
__global__ __launch_bounds__(256) void proj_kernel(
    const float* __restrict__ Xq, const float* __restrict__ Xk, const float* __restrict__ Xv,
    const float* __restrict__ Wq, const float* __restrict__ bq,
    const float* __restrict__ Wk, const float* __restrict__ bk,
    const float* __restrict__ Wv, const float* __restrict__ bv)
{
    const float* X; const float* W; const float* bias; float* Y;
    int which = blockIdx.y;
    if (which == 0)      { X = Xq; W = Wq; bias = bq; Y = g_Q; }
    else if (which == 1) { X = Xk; W = Wk; bias = bk; Y = g_K; }
    else                 { X = Xv; W = Wv; bias = bv; Y = g_V; }

    __shared__ float Xs[128][17];   // padded: col-reads spread across banks
    __shared__ float Ws[16][64];

    const int tid = threadIdx.x;
    const int tx = tid & 15;        // N groups of 4
    const int ty = tid >> 4;        // M groups of 8
    const int m0 = blockIdx.x * 128;

    float acc[8][4];
    #pragma unroll
    for (int i = 0; i < 8; i++)
        #pragma unroll
        for (int j = 0; j < 4; j++) acc[i][j] = 0.f;

    for (int kc = 0; kc < DM; kc += 16) {
        // Load X tile: 128x16 floats = 512 float4, 2 per thread (coalesced-ish)
        #pragma unroll
        for (int i = 0; i < 2; i++) {
            int f4  = i * 256 + tid;
            int row = f4 >> 2;
            int c4  = f4 & 3;
            float4 v = *(const float4*)(X + (size_t)(m0 + row) * DM + kc + c4 * 4);
            Xs[row][c4 * 4 + 0] = v.x;
            Xs[row][c4 * 4 + 1] = v.y;
            Xs[row][c4 * 4 + 2] = v.z;
            Xs[row][c4 * 4 + 3] = v.w;
        }
        // Load W tile: 16x64 floats = 256 float4, 1 per thread (coalesced)
        {
            int row = tid >> 4;
            int c4  = tid & 15;
            float4 v = *(const float4*)(W + (size_t)(kc + row) * DK + c4 * 4);
            *(float4*)&Ws[row][c4 * 4] = v;
        }
        __syncthreads();

        #pragma unroll
        for (int kk = 0; kk < 16; kk++) {
            float a[8];
            #pragma unroll
            for (int i = 0; i < 8; i++) a[i] = Xs[ty * 8 + i][kk];
            float4 bv4 = *(const float4*)&Ws[kk][tx * 4];
            #pragma unroll
            for (int i = 0; i < 8; i++) {
                acc[i][0] += a[i] * bv4.x;
                acc[i][1] += a[i] * bv4.y;
                acc[i][2] += a[i] * bv4.z;
                acc[i][3] += a[i] * bv4.w;
            }
        }
        __syncthreads();
    }

    float4 bb = *(const float4*)(bias + tx * 4);
    #pragma unroll
    for (int i = 0; i < 8; i++) {
        float4 o;
        o.x = acc[i][0] + bb.x;
        o.y = acc[i][1] + bb.y;
        o.z = acc[i][2] + bb.z;
        o.w = acc[i][3] + bb.w;
        *(float4*)(Y + (size_t)(m0 + ty * 8 + i) * DK + tx * 4) = o;
    }
}

// ---------------------------------------------------------------------------
// Causal flash attention, fp32.
// One thread per query row (BM=64 rows/block, 64 threads).
// K/V tiles of 32 rows x 64 cols in SMEM, read as broadcast float4
// (4 FMAs per LDS.128 -> FMA-pipe bound, not LSU).
// Online softmax with per-tile max; causal loop bound skips masked tiles.
// ---------------------------------------------------------------------------
__global__ __launch_bounds__(64) void attn_kernel(float* __restrict__ out)
{
    __shared__ float4 Ks[32][16];   // 32 rows x 64 floats
    __shared__ float4 Vs[32][16];

    const int tid = threadIdx.x;
    const int b   = blockIdx.y;
    // Reverse strip order: long (late) strips launch first -> better makespan
    const int strip = (gridDim.x - 1) - blockIdx.x;
    const int q0 = strip * 64;
    const int qi = q0 + tid;

    const float* Qb = g_Q + (size_t)b * SEQ * DK;
    const float* Kb = g_K + (size_t)b * SEQ * DK;
    const float* Vb = g_V + (size_t)b * SEQ * DK;

    // Load this thread's q row into registers
    float4 q[16];
    #pragma unroll
    for (int c = 0; c < 16; c++)
        q[c] = *(const float4*)(Qb + (size_t)qi * DK + c * 4);

    float acc[64];
    #pragma unroll
    for (int c = 0; c < 64; c++) acc[c] = 0.f;
    float m = -1e30f, l = 0.f;

    const int ntiles = (q0 + 64) >> 5;   // tiles covering kv in [0, q0+63]
    for (int t = 0; t < ntiles; t++) {
        const int k0 = t * 32;
        // Cooperative tile load: 512 float4 each for K and V; 8 each per thread
        #pragma unroll
        for (int i = 0; i < 8; i++) {
            int f4  = i * 64 + tid;
            int row = f4 >> 4;
            int c4  = f4 & 15;
            Ks[row][c4] = *(const float4*)(Kb + (size_t)(k0 + row) * DK + c4 * 4);
            Vs[row][c4] = *(const float4*)(Vb + (size_t)(k0 + row) * DK + c4 * 4);
        }
        __syncthreads();

        // Scores for 32 kv positions (registers), tile max
        float s[32];
        float mt = -1e30f;
        #pragma unroll
        for (int j = 0; j < 32; j++) {
            float d = 0.f;
            #pragma unroll
            for (int c = 0; c < 16; c++) {
                float4 k4 = Ks[j][c];   // broadcast across threads
                d += q[c].x * k4.x + q[c].y * k4.y + q[c].z * k4.z + q[c].w * k4.w;
            }
            d = (k0 + j <= qi) ? d * SCALE : -1e30f;
            s[j] = d;
            mt = fmaxf(mt, d);
        }

        // Online softmax: single rescale per tile
        const float mnew = fmaxf(m, mt);
        const float corr = __expf(m - mnew);
        l *= corr;
        #pragma unroll
        for (int c = 0; c < 64; c++) acc[c] *= corr;

        #pragma unroll
        for (int j = 0; j < 32; j++) {
            float p = __expf(s[j] - mnew);
            l += p;
            #pragma unroll
            for (int c = 0; c < 16; c++) {
                float4 v4 = Vs[j][c];   // broadcast across threads
                acc[c * 4 + 0] += p * v4.x;
                acc[c * 4 + 1] += p * v4.y;
                acc[c * 4 + 2] += p * v4.z;
                acc[c * 4 + 3] += p * v4.w;
            }
        }
        m = mnew;
        __syncthreads();
    }

    const float inv = 1.f / l;
    float* orow = out + ((size_t)b * SEQ + qi) * DK;
    #pragma unroll
    for (int c = 0; c < 16; c++) {
        float4 o;
        o.x = acc[c * 4 + 0] * inv;
        o.y = acc[c * 4 + 1] * inv;
        o.z = acc[c * 4 + 2] * inv;
        o.w = acc[c * 4 + 3] * inv;
        *(float4*)(orow + c * 4) = o;
    }
}

// ---------------------------------------------------------------------------
extern "C" void kernel_launch(void* const* d_in, const int* in_sizes, int n_in,
                              void* d_out, int out_size)
{
    (void)in_sizes; (void)n_in; (void)out_size;
    const float* Xq = (const float*)d_in[0];   // query_source [B,S,512]
    const float* Xk = (const float*)d_in[1];   // key_source
    const float* Xv = (const float*)d_in[2];   // value_source
    // d_in[3] = mask (triu, handled analytically)
    const float* Wq = (const float*)d_in[4];
    const float* bq = (const float*)d_in[5];
    const float* Wk = (const float*)d_in[6];
    const float* bk = (const float*)d_in[7];
    const float* Wv = (const float*)d_in[8];
    const float* bv = (const float*)d_in[9];
    float* out = (float*)d_out;

    dim3 pg(NB * SEQ / 128, 3);
    proj_kernel<<<pg, 256>>>(Xq, Xk, Xv, Wq, bq, Wk, bk, Wv, bv);

    dim3 ag(SEQ / 64, NB);     // 32 strips x 8 batches = 256 blocks
    attn_kernel<<<ag, 64>>>(out);
}